// round 4
// baseline (speedup 1.0000x reference)
#include <cuda_runtime.h>
#include <cuda_fp16.h>
#include <math_constants.h>
#include <cstdint>

#define N_TOK 131072
#define IN_F  128
#define OUT_F 256
#define NEXP  8
#define OMEGA 30.0f

#define TM 128
#define TH 256

#define SA 136              // A smem row stride (halves)
#define SB 72               // B smem row stride (halves)
#define A_TILE_B 34816      // 128*136*2
#define B_BASE_B 139264     // 4 * A_TILE_B
#define BT 4608             // B chunk tile bytes: 32*72*2
#define SMEM_BYTES (B_BASE_B + 12 * BT)   // 194560

// ---------------- scratch ----------------
__device__ int   g_count[NEXP];
__device__ int   g_tok[NEXP * N_TOK];
__device__ float g_wt [NEXP * N_TOK];
// pre-split weights: [e][d][hi/lo][ctile][k][64 cols]
__device__ __align__(128) __half g_wsp[NEXP][3][2][4][IN_F][64];

// ---------------- PTX helpers ----------------
__device__ __forceinline__ uint32_t smem_u32(const void* p) {
    uint32_t a;
    asm("{ .reg .u64 t; cvta.to.shared.u64 t, %1; cvt.u32.u64 %0, t; }" : "=r"(a) : "l"(p));
    return a;
}
__device__ __forceinline__ void ldsm_x4(uint32_t* r, uint32_t addr) {
    asm volatile("ldmatrix.sync.aligned.m8n8.x4.shared.b16 {%0,%1,%2,%3}, [%4];"
        : "=r"(r[0]), "=r"(r[1]), "=r"(r[2]), "=r"(r[3]) : "r"(addr));
}
__device__ __forceinline__ void ldsm_x4t(uint32_t* r, uint32_t addr) {
    asm volatile("ldmatrix.sync.aligned.m8n8.x4.trans.shared.b16 {%0,%1,%2,%3}, [%4];"
        : "=r"(r[0]), "=r"(r[1]), "=r"(r[2]), "=r"(r[3]) : "r"(addr));
}
__device__ __forceinline__ void mma_f16(float (&c)[4], const uint32_t (&a)[4],
                                        const uint32_t* b) {
    asm volatile("mma.sync.aligned.m16n8k16.row.col.f32.f16.f16.f32 "
        "{%0,%1,%2,%3}, {%4,%5,%6,%7}, {%8,%9}, {%0,%1,%2,%3};"
        : "+f"(c[0]), "+f"(c[1]), "+f"(c[2]), "+f"(c[3])
        : "r"(a[0]), "r"(a[1]), "r"(a[2]), "r"(a[3]), "r"(b[0]), "r"(b[1]));
}
__device__ __forceinline__ void cp16(uint32_t dst, const void* src) {
    asm volatile("cp.async.cg.shared.global [%0], [%1], 16;"
                 :: "r"(dst), "l"(src) : "memory");
}
__device__ __forceinline__ void split2(float a, float b, uint32_t& hi, uint32_t& lo) {
    __half2 h = __floats2half2_rn(a, b);
    float2 hf = __half22float2(h);
    __half2 l = __floats2half2_rn(a - hf.x, b - hf.y);
    hi = *(uint32_t*)&h;
    lo = *(uint32_t*)&l;
}

// ---------------- fast sin ----------------
__device__ __forceinline__ float fast_sin(float x) {
    float q = rintf(x * 0.3183098861837907f);
    int qi = (int)q;
    float r = fmaf(q, -3.14159274101257324f, x);
    r = fmaf(q, 8.74227765734758577e-8f, r);
    float z = r * r;
    float p = fmaf(z, -2.50521084e-8f, 2.75573192e-6f);
    p = fmaf(z, p, -1.98412698e-4f);
    p = fmaf(z, p, 8.33333333e-3f);
    p = fmaf(z, p, -1.66666667e-1f);
    float s = fmaf(r * z, p, r);
    return __int_as_float(__float_as_int(s) ^ ((qi & 1) << 31));
}

// ---------------- kernel 0: zero counters ----------------
__global__ void init_kernel() {
    if (threadIdx.x < NEXP) g_count[threadIdx.x] = 0;
}

// ---------------- kernel 1: gating + routing ----------------
__global__ void gate_kernel(const float* __restrict__ x,
                            const float* __restrict__ gw,
                            const float* __restrict__ gb) {
    __shared__ float s_gw[IN_F * NEXP];
    __shared__ float s_gb[NEXP];
    int tid = threadIdx.x;
    for (int i = tid; i < IN_F * NEXP; i += blockDim.x) s_gw[i] = gw[i];
    if (tid < NEXP) s_gb[tid] = gb[tid];
    __syncthreads();

    int warp = tid >> 5, lane = tid & 31;
    int t = blockIdx.x * 8 + warp;

    float4 xv = *(const float4*)(x + (size_t)t * IN_F + lane * 4);
    int k0 = lane * 4;
    float p[NEXP];
#pragma unroll
    for (int e = 0; e < NEXP; e++) {
        float acc = xv.x * s_gw[(k0 + 0) * NEXP + e];
        acc = fmaf(xv.y, s_gw[(k0 + 1) * NEXP + e], acc);
        acc = fmaf(xv.z, s_gw[(k0 + 2) * NEXP + e], acc);
        acc = fmaf(xv.w, s_gw[(k0 + 3) * NEXP + e], acc);
        p[e] = acc;
    }
#pragma unroll
    for (int off = 16; off; off >>= 1)
#pragma unroll
        for (int e = 0; e < NEXP; e++)
            p[e] += __shfl_xor_sync(0xffffffffu, p[e], off);

    if (lane == 0) {
        float best = -CUDART_INF_F, sec = -CUDART_INF_F;
        int bi = 0, si = 0;
#pragma unroll
        for (int e = 0; e < NEXP; e++) {
            float v = p[e] + s_gb[e];
            if (v > best) { sec = best; si = bi; best = v; bi = e; }
            else if (v > sec) { sec = v; si = e; }
        }
        float w0 = 1.0f / (1.0f + expf(sec - best));
        float w1 = 1.0f - w0;
        int p0 = atomicAdd(&g_count[bi], 1);
        g_tok[bi * N_TOK + p0] = t;
        g_wt [bi * N_TOK + p0] = w0;
        int p1 = atomicAdd(&g_count[si], 1);
        g_tok[si * N_TOK + p1] = t;
        g_wt [si * N_TOK + p1] = w1;
    }
}

// ---------------- kernel 1b: pre-split weights into fp16 hi/lo ----------------
__global__ void wsplit_kernel(const float* __restrict__ W,
                              const float* __restrict__ Wl) {
    int idx = blockIdx.x * 256 + threadIdx.x;   // 196608 total
    int c4 = idx & 15;
    int k  = (idx >> 4) & 127;
    int ct = (idx >> 11) & 3;
    int rest = idx >> 13;
    int d = rest % 3, e = rest / 3;
    const float* src = (d == 0)
        ? W  + ((size_t)e * IN_F + k) * OUT_F + ct * 64 + c4 * 4
        : Wl + ((size_t)e * IN_F + k) * (2 * OUT_F) + (d == 2 ? OUT_F : 0) + ct * 64 + c4 * 4;
    float4 v = *(const float4*)src;
    uint32_t h01, l01, h23, l23;
    split2(v.x, v.y, h01, l01);
    split2(v.z, v.w, h23, l23);
    uint2 uh; uh.x = h01; uh.y = h23;
    uint2 ul; ul.x = l01; ul.y = l23;
    *(uint2*)&g_wsp[e][d][0][ct][k][c4 * 4] = uh;
    *(uint2*)&g_wsp[e][d][1][ct][k][c4 * 4] = ul;
}

// ---------------- kernel 2: pipelined split-fp16 mma.sync + fused sin + RED ----------------
__global__ __launch_bounds__(TH) void expert_kernel(
    const float* __restrict__ x,  const float* __restrict__ lat,
    const float* __restrict__ b,  const float* __restrict__ bl,
    float* __restrict__ out)
{
    extern __shared__ __align__(16) __half sm[];
    __shared__ int   s_ent[TM];
    __shared__ float s_w[TM];

    int e = blockIdx.y;
    int cnt = g_count[e];
    int m0 = blockIdx.x * TM;
    if (m0 >= cnt) return;
    int rows = min(TM, cnt - m0);
    int tid = threadIdx.x;
    int w = tid >> 5, lane = tid & 31;

    uint32_t smu = smem_u32(sm);
    const __half* wb = &g_wsp[e][0][0][0][0][0];

    // ---- issue cp.async for chunks 0,1 immediately (overlaps A staging)
#pragma unroll
    for (int j = 0; j < 2; j++) {
        int ct2 = 0, kc0 = j * 32, buf2 = j & 1;
#pragma unroll
        for (int t = 0; t < 6; t++) {
            int u = t * 256 + tid;
            int un = u & 7, r = (u >> 3) & 31, h = (u >> 8) & 1, d = u >> 9;
            const __half* src = wb + (size_t)((((d * 2 + h) * 4 + ct2) * 128) + kc0 + r) * 64 + un * 8;
            uint32_t dst = smu + B_BASE_B
                         + (uint32_t)((buf2 * 6 + d * 2 + h) * BT + r * 144 + un * 16);
            cp16(dst, src);
        }
        asm volatile("cp.async.commit_group;" ::: "memory");
    }

    if (tid < TM) {
        int ent = (tid < rows) ? g_tok[e * N_TOK + m0 + tid] : 0;
        s_ent[tid] = ent;
        s_w[tid]   = (tid < rows) ? g_wt[e * N_TOK + m0 + tid] : 0.0f;
    }
    __syncthreads();

    // ---- stage A: gather x/lat rows, split fp16 hi/lo (once per block)
#pragma unroll
    for (int s2 = 0; s2 < 2; s2++) {
        const float* src = s2 ? lat : x;
        __half* hiT = sm + (size_t)(s2 * 2) * (128 * SA);
#pragma unroll
        for (int it = 0; it < 16; it++) {
            int idx = it * TH + tid;
            int m = idx >> 5, k = (idx & 31) * 4;
            int tok = s_ent[m];
            float4 v = *(const float4*)(src + (size_t)tok * IN_F + k);
            uint32_t h01, l01, h23, l23;
            split2(v.x, v.y, h01, l01);
            split2(v.z, v.w, h23, l23);
            __half* p = hiT + m * SA + k;
            uint2 uh; uh.x = h01; uh.y = h23;
            uint2 ul; ul.x = l01; ul.y = l23;
            *(uint2*)p = uh;
            *(uint2*)(p + 128 * SA) = ul;
        }
    }

    int wm = w >> 1, wn = w & 1;
    uint32_t aoff0 = (uint32_t)(((wm * 32 + (lane & 15)) * SA + (lane >> 4) * 8) * 2);
    uint32_t aoff1 = aoff0 + 16 * SA * 2;
    uint32_t bcon = (uint32_t)((((lane & 7) + ((lane >> 3) & 1) * 8) * SB
                               + ((lane >> 4) & 1) * 8 + wn * 32) * 2);

    float acc[3][2][4][4];
#pragma unroll
    for (int d = 0; d < 3; d++)
#pragma unroll
        for (int mf = 0; mf < 2; mf++)
#pragma unroll
            for (int nf = 0; nf < 4; nf++)
#pragma unroll
                for (int q = 0; q < 4; q++) acc[d][mf][nf][q] = 0.0f;

#pragma unroll 1
    for (int i = 0; i < 16; i++) {
        if (i == 15) asm volatile("cp.async.wait_group 0;" ::: "memory");
        else         asm volatile("cp.async.wait_group 1;" ::: "memory");
        __syncthreads();

        int buf = i & 1, c = i & 3, ct = i >> 2;
        uint32_t bB = smu + B_BASE_B + (uint32_t)(buf * 6) * BT;

#pragma unroll
        for (int kl = 0; kl < 2; kl++) {
            uint32_t kby = (uint32_t)((c * 32 + kl * 16) * 2);
            uint32_t kbb = (uint32_t)(kl * 16 * SB * 2);
            uint32_t AH[2][4], AL[2][4];
            uint32_t bh[8], blo[8];

            // x fragments -> d0
            ldsm_x4(AH[0], smu + aoff0 + kby);
            ldsm_x4(AH[1], smu + aoff1 + kby);
            ldsm_x4(AL[0], smu + A_TILE_B + aoff0 + kby);
            ldsm_x4(AL[1], smu + A_TILE_B + aoff1 + kby);
            {
                uint32_t bhi = bB;
                uint32_t blo_b = bB + BT;
                ldsm_x4t(&bh[0],  bhi + bcon + kbb);
                ldsm_x4t(&bh[4],  bhi + bcon + kbb + 32);
                ldsm_x4t(&blo[0], blo_b + bcon + kbb);
                ldsm_x4t(&blo[4], blo_b + bcon + kbb + 32);
#pragma unroll
                for (int mf = 0; mf < 2; mf++)
#pragma unroll
                    for (int nf = 0; nf < 4; nf++) {
                        mma_f16(acc[0][mf][nf], AH[mf], &bh[nf * 2]);
                        mma_f16(acc[0][mf][nf], AH[mf], &blo[nf * 2]);
                        mma_f16(acc[0][mf][nf], AL[mf], &bh[nf * 2]);
                    }
            }
            // lat fragments -> d1, d2
            ldsm_x4(AH[0], smu + 2 * A_TILE_B + aoff0 + kby);
            ldsm_x4(AH[1], smu + 2 * A_TILE_B + aoff1 + kby);
            ldsm_x4(AL[0], smu + 3 * A_TILE_B + aoff0 + kby);
            ldsm_x4(AL[1], smu + 3 * A_TILE_B + aoff1 + kby);
#pragma unroll
            for (int d = 1; d < 3; d++) {
                uint32_t bhi = bB + (uint32_t)(d * 2) * BT;
                uint32_t blo_b = bhi + BT;
                ldsm_x4t(&bh[0],  bhi + bcon + kbb);
                ldsm_x4t(&bh[4],  bhi + bcon + kbb + 32);
                ldsm_x4t(&blo[0], blo_b + bcon + kbb);
                ldsm_x4t(&blo[4], blo_b + bcon + kbb + 32);
#pragma unroll
                for (int mf = 0; mf < 2; mf++)
#pragma unroll
                    for (int nf = 0; nf < 4; nf++) {
                        mma_f16(acc[d][mf][nf], AH[mf], &bh[nf * 2]);
                        mma_f16(acc[d][mf][nf], AH[mf], &blo[nf * 2]);
                        mma_f16(acc[d][mf][nf], AL[mf], &bh[nf * 2]);
                    }
            }
        }
        __syncthreads();

        // ---- issue chunk i+2 into buffer buf
        if (i < 14) {
            int j = i + 2;
            int ct2 = j >> 2, kc0 = (j & 3) * 32, buf2 = j & 1;
#pragma unroll
            for (int t = 0; t < 6; t++) {
                int u = t * 256 + tid;
                int un = u & 7, r = (u >> 3) & 31, h = (u >> 8) & 1, d = u >> 9;
                const __half* src = wb + (size_t)((((d * 2 + h) * 4 + ct2) * 128) + kc0 + r) * 64 + un * 8;
                uint32_t dst = smu + B_BASE_B
                             + (uint32_t)((buf2 * 6 + d * 2 + h) * BT + r * 144 + un * 16);
                cp16(dst, src);
            }
            asm volatile("cp.async.commit_group;" ::: "memory");
        }

        // ---- epilogue at ctile end: bias + sin + gate weight + RED into out
        if (c == 3) {
            int cb0 = ct * 64 + wn * 32 + 2 * (lane & 3);
            float2 Bb[4], Bs[4], Bt2[4];
#pragma unroll
            for (int nf = 0; nf < 4; nf++) {
                Bb[nf]  = *(const float2*)(b  + (size_t)e * OUT_F + cb0 + nf * 8);
                Bs[nf]  = *(const float2*)(bl + (size_t)e * 2 * OUT_F + cb0 + nf * 8);
                Bt2[nf] = *(const float2*)(bl + (size_t)e * 2 * OUT_F + OUT_F + cb0 + nf * 8);
            }
#pragma unroll
            for (int mf = 0; mf < 2; mf++)
#pragma unroll
                for (int hh = 0; hh < 2; hh++) {
                    int row = wm * 32 + mf * 16 + (lane >> 2) + 8 * hh;
                    if (row < rows) {
                        int tok = s_ent[row];
                        float wt = s_w[row];
                        float* gp = out + (size_t)tok * OUT_F + cb0;
#pragma unroll
                        for (int nf = 0; nf < 4; nf++) {
                            float hv0 = acc[0][mf][nf][2 * hh + 0] + Bb[nf].x;
                            float hv1 = acc[0][mf][nf][2 * hh + 1] + Bb[nf].y;
                            float sc0 = acc[1][mf][nf][2 * hh + 0] + Bs[nf].x;
                            float sc1 = acc[1][mf][nf][2 * hh + 1] + Bs[nf].y;
                            float sh0 = acc[2][mf][nf][2 * hh + 0] + Bt2[nf].x;
                            float sh1 = acc[2][mf][nf][2 * hh + 1] + Bt2[nf].y;
                            atomicAdd(gp + nf * 8,     wt * fast_sin(fmaf(OMEGA * hv0, sc0, sh0)));
                            atomicAdd(gp + nf * 8 + 1, wt * fast_sin(fmaf(OMEGA * hv1, sc1, sh1)));
                        }
                    }
                }
            // reset accumulators for next ctile
#pragma unroll
            for (int d = 0; d < 3; d++)
#pragma unroll
                for (int mf = 0; mf < 2; mf++)
#pragma unroll
                    for (int nf = 0; nf < 4; nf++)
#pragma unroll
                        for (int q = 0; q < 4; q++) acc[d][mf][nf][q] = 0.0f;
        }
    }
}

// ---------------- launch ----------------
extern "C" void kernel_launch(void* const* d_in, const int* in_sizes, int n_in,
                              void* d_out, int out_size) {
    const float* x   = (const float*)d_in[0];
    const float* lat = (const float*)d_in[1];
    const float* gw  = (const float*)d_in[2];
    const float* gb  = (const float*)d_in[3];
    const float* W   = (const float*)d_in[4];
    const float* b   = (const float*)d_in[5];
    const float* Wl  = (const float*)d_in[6];
    const float* bl  = (const float*)d_in[7];
    float* out = (float*)d_out;

    cudaFuncSetAttribute(expert_kernel,
                         cudaFuncAttributeMaxDynamicSharedMemorySize, SMEM_BYTES);

    init_kernel<<<1, 32>>>();
    gate_kernel<<<N_TOK / 8, 256>>>(x, gw, gb);
    wsplit_kernel<<<768, 256>>>(W, Wl);
    cudaMemsetAsync(out, 0, (size_t)N_TOK * OUT_F * sizeof(float));
    cudaMemcpyAsync(out + (size_t)N_TOK * OUT_F, lat,
                    (size_t)N_TOK * IN_F * sizeof(float),
                    cudaMemcpyDeviceToDevice);
    expert_kernel<<<dim3(N_TOK / TM, NEXP), TH, SMEM_BYTES>>>(x, lat, b, bl, out);
}

// round 5
// speedup vs baseline: 1.0140x; 1.0140x over previous
#include <cuda_runtime.h>
#include <cuda_fp16.h>
#include <math_constants.h>
#include <cstdint>

#define N_TOK 131072
#define IN_F  128
#define OUT_F 256
#define NEXP  8
#define OMEGA 30.0f

#define TM 128
#define TH 512

#define SA 136              // A smem row stride (halves)
#define SB 72               // B smem row stride (halves)
#define A_TILE_B 34816      // 128*136*2
#define B_BASE_B 139264     // 4 * A_TILE_B
#define BT 4608             // B chunk tile bytes: 32*72*2
#define SMEM_BYTES (B_BASE_B + 12 * BT)   // 194560

// ---------------- scratch ----------------
__device__ int   g_count[NEXP];
__device__ int   g_tok[NEXP * N_TOK];     // (slot<<24) | token
__device__ float g_wt [NEXP * N_TOK];
__device__ float g_part[2][N_TOK][OUT_F];
// pre-split weights: [e][d][hi/lo][ctile][k][64 cols]
__device__ __align__(128) __half g_wsp[NEXP][3][2][4][IN_F][64];

// ---------------- PTX helpers ----------------
__device__ __forceinline__ uint32_t smem_u32(const void* p) {
    uint32_t a;
    asm("{ .reg .u64 t; cvta.to.shared.u64 t, %1; cvt.u32.u64 %0, t; }" : "=r"(a) : "l"(p));
    return a;
}
__device__ __forceinline__ void ldsm_x4(uint32_t* r, uint32_t addr) {
    asm volatile("ldmatrix.sync.aligned.m8n8.x4.shared.b16 {%0,%1,%2,%3}, [%4];"
        : "=r"(r[0]), "=r"(r[1]), "=r"(r[2]), "=r"(r[3]) : "r"(addr));
}
__device__ __forceinline__ void ldsm_x4t(uint32_t* r, uint32_t addr) {
    asm volatile("ldmatrix.sync.aligned.m8n8.x4.trans.shared.b16 {%0,%1,%2,%3}, [%4];"
        : "=r"(r[0]), "=r"(r[1]), "=r"(r[2]), "=r"(r[3]) : "r"(addr));
}
__device__ __forceinline__ void mma_f16(float (&c)[4], const uint32_t (&a)[4],
                                        const uint32_t* b) {
    asm volatile("mma.sync.aligned.m16n8k16.row.col.f32.f16.f16.f32 "
        "{%0,%1,%2,%3}, {%4,%5,%6,%7}, {%8,%9}, {%0,%1,%2,%3};"
        : "+f"(c[0]), "+f"(c[1]), "+f"(c[2]), "+f"(c[3])
        : "r"(a[0]), "r"(a[1]), "r"(a[2]), "r"(a[3]), "r"(b[0]), "r"(b[1]));
}
__device__ __forceinline__ void cp16(uint32_t dst, const void* src) {
    asm volatile("cp.async.cg.shared.global [%0], [%1], 16;"
                 :: "r"(dst), "l"(src) : "memory");
}
__device__ __forceinline__ void split2(float a, float b, uint32_t& hi, uint32_t& lo) {
    __half2 h = __floats2half2_rn(a, b);
    float2 hf = __half22float2(h);
    __half2 l = __floats2half2_rn(a - hf.x, b - hf.y);
    hi = *(uint32_t*)&h;
    lo = *(uint32_t*)&l;
}

// ---------------- fast sin ----------------
__device__ __forceinline__ float fast_sin(float x) {
    float q = rintf(x * 0.3183098861837907f);
    int qi = (int)q;
    float r = fmaf(q, -3.14159274101257324f, x);
    r = fmaf(q, 8.74227765734758577e-8f, r);
    float z = r * r;
    float p = fmaf(z, -2.50521084e-8f, 2.75573192e-6f);
    p = fmaf(z, p, -1.98412698e-4f);
    p = fmaf(z, p, 8.33333333e-3f);
    p = fmaf(z, p, -1.66666667e-1f);
    float s = fmaf(r * z, p, r);
    return __int_as_float(__float_as_int(s) ^ ((qi & 1) << 31));
}

// ---------------- kernel 0: zero counters ----------------
__global__ void init_kernel() {
    if (threadIdx.x < NEXP) g_count[threadIdx.x] = 0;
}

// ---------------- kernel 1: gating + routing ----------------
__global__ void gate_kernel(const float* __restrict__ x,
                            const float* __restrict__ gw,
                            const float* __restrict__ gb) {
    __shared__ float s_gw[IN_F * NEXP];
    __shared__ float s_gb[NEXP];
    int tid = threadIdx.x;
    for (int i = tid; i < IN_F * NEXP; i += blockDim.x) s_gw[i] = gw[i];
    if (tid < NEXP) s_gb[tid] = gb[tid];
    __syncthreads();

    int warp = tid >> 5, lane = tid & 31;
    int t = blockIdx.x * 8 + warp;

    float4 xv = *(const float4*)(x + (size_t)t * IN_F + lane * 4);
    int k0 = lane * 4;
    float p[NEXP];
#pragma unroll
    for (int e = 0; e < NEXP; e++) {
        float acc = xv.x * s_gw[(k0 + 0) * NEXP + e];
        acc = fmaf(xv.y, s_gw[(k0 + 1) * NEXP + e], acc);
        acc = fmaf(xv.z, s_gw[(k0 + 2) * NEXP + e], acc);
        acc = fmaf(xv.w, s_gw[(k0 + 3) * NEXP + e], acc);
        p[e] = acc;
    }
#pragma unroll
    for (int off = 16; off; off >>= 1)
#pragma unroll
        for (int e = 0; e < NEXP; e++)
            p[e] += __shfl_xor_sync(0xffffffffu, p[e], off);

    if (lane == 0) {
        float best = -CUDART_INF_F, sec = -CUDART_INF_F;
        int bi = 0, si = 0;
#pragma unroll
        for (int e = 0; e < NEXP; e++) {
            float v = p[e] + s_gb[e];
            if (v > best) { sec = best; si = bi; best = v; bi = e; }
            else if (v > sec) { sec = v; si = e; }
        }
        float w0 = 1.0f / (1.0f + expf(sec - best));
        float w1 = 1.0f - w0;
        int p0 = atomicAdd(&g_count[bi], 1);
        g_tok[bi * N_TOK + p0] = t;
        g_wt [bi * N_TOK + p0] = w0;
        int p1 = atomicAdd(&g_count[si], 1);
        g_tok[si * N_TOK + p1] = t | (1 << 24);
        g_wt [si * N_TOK + p1] = w1;
    }
}

// ---------------- kernel 1b: pre-split weights into fp16 hi/lo ----------------
__global__ void wsplit_kernel(const float* __restrict__ W,
                              const float* __restrict__ Wl) {
    int idx = blockIdx.x * 256 + threadIdx.x;   // 196608 total
    int c4 = idx & 15;
    int k  = (idx >> 4) & 127;
    int ct = (idx >> 11) & 3;
    int rest = idx >> 13;
    int d = rest % 3, e = rest / 3;
    const float* src = (d == 0)
        ? W  + ((size_t)e * IN_F + k) * OUT_F + ct * 64 + c4 * 4
        : Wl + ((size_t)e * IN_F + k) * (2 * OUT_F) + (d == 2 ? OUT_F : 0) + ct * 64 + c4 * 4;
    float4 v = *(const float4*)src;
    uint32_t h01, l01, h23, l23;
    split2(v.x, v.y, h01, l01);
    split2(v.z, v.w, h23, l23);
    uint2 uh; uh.x = h01; uh.y = h23;
    uint2 ul; ul.x = l01; ul.y = l23;
    *(uint2*)&g_wsp[e][d][0][ct][k][c4 * 4] = uh;
    *(uint2*)&g_wsp[e][d][1][ct][k][c4 * 4] = ul;
}

// ---------------- kernel 2: pipelined split-fp16 mma.sync + fused sin ----------------
// 16 warps: wm = w>>2 (32-row band), wn = w&3 (16-col slice of the 64-col ctile)
__global__ __launch_bounds__(TH, 1) void expert_kernel(
    const float* __restrict__ x,  const float* __restrict__ lat,
    const float* __restrict__ b,  const float* __restrict__ bl)
{
    extern __shared__ __align__(16) __half sm[];
    __shared__ int   s_ent[TM];
    __shared__ float s_w[TM];

    int e = blockIdx.y;
    int cnt = g_count[e];
    int m0 = blockIdx.x * TM;
    if (m0 >= cnt) return;
    int rows = min(TM, cnt - m0);
    int tid = threadIdx.x;
    int w = tid >> 5, lane = tid & 31;

    uint32_t smu = smem_u32(sm);
    const __half* wb = &g_wsp[e][0][0][0][0][0];

    // ---- issue cp.async for chunks 0,1 immediately
#pragma unroll
    for (int j = 0; j < 2; j++) {
        int kc0 = j * 32, buf2 = j & 1;
#pragma unroll
        for (int t = 0; t < 3; t++) {
            int u = t * TH + tid;
            int un = u & 7, r = (u >> 3) & 31, h = (u >> 8) & 1, d = u >> 9;
            const __half* src = wb + (size_t)(((d * 2 + h) * 4 * 128) + kc0 + r) * 64 + un * 8;
            uint32_t dst = smu + B_BASE_B
                         + (uint32_t)((buf2 * 6 + d * 2 + h) * BT + r * 144 + un * 16);
            cp16(dst, src);
        }
        asm volatile("cp.async.commit_group;" ::: "memory");
    }

    if (tid < TM) {
        int ent = (tid < rows) ? g_tok[e * N_TOK + m0 + tid] : 0;
        s_ent[tid] = ent;
        s_w[tid]   = (tid < rows) ? g_wt[e * N_TOK + m0 + tid] : 0.0f;
    }
    __syncthreads();

    // ---- stage A: gather x/lat rows, split fp16 hi/lo (once per block)
#pragma unroll
    for (int s2 = 0; s2 < 2; s2++) {
        const float* src = s2 ? lat : x;
        __half* hiT = sm + (size_t)(s2 * 2) * (128 * SA);
#pragma unroll
        for (int it = 0; it < 8; it++) {
            int idx = it * TH + tid;
            int m = idx >> 5, k = (idx & 31) * 4;
            int tok = s_ent[m] & 0xFFFFFF;
            float4 v = *(const float4*)(src + (size_t)tok * IN_F + k);
            uint32_t h01, l01, h23, l23;
            split2(v.x, v.y, h01, l01);
            split2(v.z, v.w, h23, l23);
            __half* p = hiT + m * SA + k;
            uint2 uh; uh.x = h01; uh.y = h23;
            uint2 ul; ul.x = l01; ul.y = l23;
            *(uint2*)p = uh;
            *(uint2*)(p + 128 * SA) = ul;
        }
    }

    int wm = w >> 2, wn = w & 3;
    uint32_t aoff0 = (uint32_t)(((wm * 32 + (lane & 15)) * SA + (lane >> 4) * 8) * 2);
    uint32_t aoff1 = aoff0 + 16 * SA * 2;
    uint32_t bcon = (uint32_t)((((lane & 7) + ((lane >> 3) & 1) * 8) * SB
                               + ((lane >> 4) & 1) * 8 + wn * 16) * 2);

    float acc[3][2][2][4];
#pragma unroll
    for (int d = 0; d < 3; d++)
#pragma unroll
        for (int mf = 0; mf < 2; mf++)
#pragma unroll
            for (int nf = 0; nf < 2; nf++)
#pragma unroll
                for (int q = 0; q < 4; q++) acc[d][mf][nf][q] = 0.0f;

#pragma unroll 1
    for (int i = 0; i < 16; i++) {
        if (i == 15) asm volatile("cp.async.wait_group 0;" ::: "memory");
        else         asm volatile("cp.async.wait_group 1;" ::: "memory");
        __syncthreads();

        int buf = i & 1, c = i & 3, ct = i >> 2;
        uint32_t bB = smu + B_BASE_B + (uint32_t)(buf * 6) * BT;

#pragma unroll
        for (int kl = 0; kl < 2; kl++) {
            uint32_t kby = (uint32_t)((c * 32 + kl * 16) * 2);
            uint32_t kbb = (uint32_t)(kl * 16 * SB * 2);
            uint32_t AH[2][4], AL[2][4];
            uint32_t bh[4], blo[4];

            // x fragments -> d0
            ldsm_x4(AH[0], smu + aoff0 + kby);
            ldsm_x4(AH[1], smu + aoff1 + kby);
            ldsm_x4(AL[0], smu + A_TILE_B + aoff0 + kby);
            ldsm_x4(AL[1], smu + A_TILE_B + aoff1 + kby);
            {
                ldsm_x4t(bh,  bB + bcon + kbb);
                ldsm_x4t(blo, bB + BT + bcon + kbb);
#pragma unroll
                for (int mf = 0; mf < 2; mf++)
#pragma unroll
                    for (int nf = 0; nf < 2; nf++) {
                        mma_f16(acc[0][mf][nf], AH[mf], &bh[nf * 2]);
                        mma_f16(acc[0][mf][nf], AH[mf], &blo[nf * 2]);
                        mma_f16(acc[0][mf][nf], AL[mf], &bh[nf * 2]);
                    }
            }
            // lat fragments -> d1, d2
            ldsm_x4(AH[0], smu + 2 * A_TILE_B + aoff0 + kby);
            ldsm_x4(AH[1], smu + 2 * A_TILE_B + aoff1 + kby);
            ldsm_x4(AL[0], smu + 3 * A_TILE_B + aoff0 + kby);
            ldsm_x4(AL[1], smu + 3 * A_TILE_B + aoff1 + kby);
#pragma unroll
            for (int d = 1; d < 3; d++) {
                uint32_t bhi = bB + (uint32_t)(d * 2) * BT;
                ldsm_x4t(bh,  bhi + bcon + kbb);
                ldsm_x4t(blo, bhi + BT + bcon + kbb);
#pragma unroll
                for (int mf = 0; mf < 2; mf++)
#pragma unroll
                    for (int nf = 0; nf < 2; nf++) {
                        mma_f16(acc[d][mf][nf], AH[mf], &bh[nf * 2]);
                        mma_f16(acc[d][mf][nf], AH[mf], &blo[nf * 2]);
                        mma_f16(acc[d][mf][nf], AL[mf], &bh[nf * 2]);
                    }
            }
        }
        __syncthreads();

        // ---- issue chunk i+2 into buffer buf
        if (i < 14) {
            int j = i + 2;
            int ct2 = j >> 2, kc0 = (j & 3) * 32, buf2 = j & 1;
#pragma unroll
            for (int t = 0; t < 3; t++) {
                int u = t * TH + tid;
                int un = u & 7, r = (u >> 3) & 31, h = (u >> 8) & 1, d = u >> 9;
                const __half* src = wb + (size_t)((((d * 2 + h) * 4 + ct2) * 128) + kc0 + r) * 64 + un * 8;
                uint32_t dst = smu + B_BASE_B
                             + (uint32_t)((buf2 * 6 + d * 2 + h) * BT + r * 144 + un * 16);
                cp16(dst, src);
            }
            asm volatile("cp.async.commit_group;" ::: "memory");
        }

        // ---- epilogue at ctile end: bias + sin + gate weight + float2 stores
        if (c == 3) {
            int cb0 = ct * 64 + wn * 16 + 2 * (lane & 3);
            float2 Bb[2], Bs[2], Bt2[2];
#pragma unroll
            for (int nf = 0; nf < 2; nf++) {
                Bb[nf]  = *(const float2*)(b  + (size_t)e * OUT_F + cb0 + nf * 8);
                Bs[nf]  = *(const float2*)(bl + (size_t)e * 2 * OUT_F + cb0 + nf * 8);
                Bt2[nf] = *(const float2*)(bl + (size_t)e * 2 * OUT_F + OUT_F + cb0 + nf * 8);
            }
#pragma unroll
            for (int mf = 0; mf < 2; mf++)
#pragma unroll
                for (int hh = 0; hh < 2; hh++) {
                    int row = wm * 32 + mf * 16 + (lane >> 2) + 8 * hh;
                    if (row < rows) {
                        int ent = s_ent[row];
                        int tok = ent & 0xFFFFFF, sl = (ent >> 24) & 1;
                        float wt = s_w[row];
                        float* gp = &g_part[sl][tok][cb0];
#pragma unroll
                        for (int nf = 0; nf < 2; nf++) {
                            float hv0 = acc[0][mf][nf][2 * hh + 0] + Bb[nf].x;
                            float hv1 = acc[0][mf][nf][2 * hh + 1] + Bb[nf].y;
                            float sc0 = acc[1][mf][nf][2 * hh + 0] + Bs[nf].x;
                            float sc1 = acc[1][mf][nf][2 * hh + 1] + Bs[nf].y;
                            float sh0 = acc[2][mf][nf][2 * hh + 0] + Bt2[nf].x;
                            float sh1 = acc[2][mf][nf][2 * hh + 1] + Bt2[nf].y;
                            float2 o;
                            o.x = wt * fast_sin(fmaf(OMEGA * hv0, sc0, sh0));
                            o.y = wt * fast_sin(fmaf(OMEGA * hv1, sc1, sh1));
                            *(float2*)(gp + nf * 8) = o;
                        }
                    }
                }
            // reset accumulators for next ctile
#pragma unroll
            for (int d = 0; d < 3; d++)
#pragma unroll
                for (int mf = 0; mf < 2; mf++)
#pragma unroll
                    for (int nf = 0; nf < 2; nf++)
#pragma unroll
                        for (int q = 0; q < 4; q++) acc[d][mf][nf][q] = 0.0f;
        }
    }
}

// ---------------- kernel 3: combine slot contributions ----------------
__global__ void combine_kernel(float* __restrict__ out) {
    size_t i = (size_t)blockIdx.x * blockDim.x + threadIdx.x;
    const float4* p0 = (const float4*)&g_part[0][0][0];
    const float4* p1 = (const float4*)&g_part[1][0][0];
    float4 a = p0[i], c = p1[i];
    ((float4*)out)[i] = make_float4(a.x + c.x, a.y + c.y, a.z + c.z, a.w + c.w);
}

// ---------------- launch ----------------
extern "C" void kernel_launch(void* const* d_in, const int* in_sizes, int n_in,
                              void* d_out, int out_size) {
    const float* x   = (const float*)d_in[0];
    const float* lat = (const float*)d_in[1];
    const float* gw  = (const float*)d_in[2];
    const float* gb  = (const float*)d_in[3];
    const float* W   = (const float*)d_in[4];
    const float* b   = (const float*)d_in[5];
    const float* Wl  = (const float*)d_in[6];
    const float* bl  = (const float*)d_in[7];
    float* out = (float*)d_out;

    cudaFuncSetAttribute(expert_kernel,
                         cudaFuncAttributeMaxDynamicSharedMemorySize, SMEM_BYTES);

    init_kernel<<<1, 32>>>();
    gate_kernel<<<N_TOK / 8, 256>>>(x, gw, gb);
    wsplit_kernel<<<768, 256>>>(W, Wl);
    cudaMemcpyAsync(out + (size_t)N_TOK * OUT_F, lat,
                    (size_t)N_TOK * IN_F * sizeof(float),
                    cudaMemcpyDeviceToDevice);
    expert_kernel<<<dim3(N_TOK / TM, NEXP), TH, SMEM_BYTES>>>(x, lat, b, bl);
    combine_kernel<<<(N_TOK * OUT_F / 4) / 256, 256>>>(out);
}

// round 6
// speedup vs baseline: 1.0773x; 1.0624x over previous
#include <cuda_runtime.h>
#include <cuda_fp16.h>
#include <math_constants.h>
#include <cstdint>

#define N_TOK 131072
#define IN_F  128
#define OUT_F 256
#define NEXP  8
#define OMEGA 30.0f

#define TM 128
#define TH 512

#define SA 136              // A smem row stride (halves)
#define SB 72               // B smem row stride (halves)
#define A_TILE_B 34816      // 128*136*2
#define B_BASE_B 139264     // 4 * A_TILE_B
#define BT 4608             // one B tile: 32*72*2
#define CH (6 * BT)         // one chunk: 6 tiles (3 outputs x hi/lo)
#define SMEM_BYTES (B_BASE_B + 3 * CH)   // 222208

// ---------------- scratch ----------------
__device__ int      g_count[NEXP];
__device__ int      g_tok[NEXP * N_TOK];     // (slot<<24) | token
__device__ float    g_wt [NEXP * N_TOK];
__device__ float    g_part[2][N_TOK][OUT_F];
__device__ uint32_t g_re[N_TOK];             // e0 | (e1<<8)
__device__ float    g_w0[N_TOK];
// pre-split weights: [e][d][hi/lo][ctile][k][64 cols]
__device__ __align__(128) __half g_wsp[NEXP][3][2][4][IN_F][64];

// ---------------- PTX helpers ----------------
__device__ __forceinline__ uint32_t smem_u32(const void* p) {
    uint32_t a;
    asm("{ .reg .u64 t; cvta.to.shared.u64 t, %1; cvt.u32.u64 %0, t; }" : "=r"(a) : "l"(p));
    return a;
}
__device__ __forceinline__ void ldsm_x4(uint32_t* r, uint32_t addr) {
    asm volatile("ldmatrix.sync.aligned.m8n8.x4.shared.b16 {%0,%1,%2,%3}, [%4];"
        : "=r"(r[0]), "=r"(r[1]), "=r"(r[2]), "=r"(r[3]) : "r"(addr));
}
__device__ __forceinline__ void ldsm_x4t(uint32_t* r, uint32_t addr) {
    asm volatile("ldmatrix.sync.aligned.m8n8.x4.trans.shared.b16 {%0,%1,%2,%3}, [%4];"
        : "=r"(r[0]), "=r"(r[1]), "=r"(r[2]), "=r"(r[3]) : "r"(addr));
}
__device__ __forceinline__ void mma_f16(float (&c)[4], const uint32_t (&a)[4],
                                        const uint32_t* b) {
    asm volatile("mma.sync.aligned.m16n8k16.row.col.f32.f16.f16.f32 "
        "{%0,%1,%2,%3}, {%4,%5,%6,%7}, {%8,%9}, {%0,%1,%2,%3};"
        : "+f"(c[0]), "+f"(c[1]), "+f"(c[2]), "+f"(c[3])
        : "r"(a[0]), "r"(a[1]), "r"(a[2]), "r"(a[3]), "r"(b[0]), "r"(b[1]));
}
__device__ __forceinline__ void cp16(uint32_t dst, const void* src) {
    asm volatile("cp.async.cg.shared.global [%0], [%1], 16;"
                 :: "r"(dst), "l"(src) : "memory");
}
__device__ __forceinline__ void split2(float a, float b, uint32_t& hi, uint32_t& lo) {
    __half2 h = __floats2half2_rn(a, b);
    float2 hf = __half22float2(h);
    __half2 l = __floats2half2_rn(a - hf.x, b - hf.y);
    hi = *(uint32_t*)&h;
    lo = *(uint32_t*)&l;
}

// ---------------- fast sin ----------------
__device__ __forceinline__ float fast_sin(float x) {
    float q = rintf(x * 0.3183098861837907f);
    int qi = (int)q;
    float r = fmaf(q, -3.14159274101257324f, x);
    r = fmaf(q, 8.74227765734758577e-8f, r);
    float z = r * r;
    float p = fmaf(z, -2.50521084e-8f, 2.75573192e-6f);
    p = fmaf(z, p, -1.98412698e-4f);
    p = fmaf(z, p, 8.33333333e-3f);
    p = fmaf(z, p, -1.66666667e-1f);
    float s = fmaf(r * z, p, r);
    return __int_as_float(__float_as_int(s) ^ ((qi & 1) << 31));
}

// ---------------- kernel 0: zero counters ----------------
__global__ void init_kernel() {
    if (threadIdx.x < NEXP) g_count[threadIdx.x] = 0;
}

// ---------------- kernel 1: routing (no atomics) ----------------
__global__ void route_kernel(const float* __restrict__ x,
                             const float* __restrict__ gw,
                             const float* __restrict__ gb) {
    __shared__ float s_gw[IN_F * NEXP];
    __shared__ float s_gb[NEXP];
    int tid = threadIdx.x;
    for (int i = tid; i < IN_F * NEXP; i += blockDim.x) s_gw[i] = gw[i];
    if (tid < NEXP) s_gb[tid] = gb[tid];
    __syncthreads();

    int warp = tid >> 5, lane = tid & 31;
    int t = blockIdx.x * 8 + warp;

    float4 xv = *(const float4*)(x + (size_t)t * IN_F + lane * 4);
    int k0 = lane * 4;
    float p[NEXP];
#pragma unroll
    for (int e = 0; e < NEXP; e++) {
        float acc = xv.x * s_gw[(k0 + 0) * NEXP + e];
        acc = fmaf(xv.y, s_gw[(k0 + 1) * NEXP + e], acc);
        acc = fmaf(xv.z, s_gw[(k0 + 2) * NEXP + e], acc);
        acc = fmaf(xv.w, s_gw[(k0 + 3) * NEXP + e], acc);
        p[e] = acc;
    }
#pragma unroll
    for (int off = 16; off; off >>= 1)
#pragma unroll
        for (int e = 0; e < NEXP; e++)
            p[e] += __shfl_xor_sync(0xffffffffu, p[e], off);

    if (lane == 0) {
        float best = -CUDART_INF_F, sec = -CUDART_INF_F;
        int bi = 0, si = 0;
#pragma unroll
        for (int e = 0; e < NEXP; e++) {
            float v = p[e] + s_gb[e];
            if (v > best) { sec = best; si = bi; best = v; bi = e; }
            else if (v > sec) { sec = v; si = e; }
        }
        g_re[t] = (uint32_t)bi | ((uint32_t)si << 8);
        g_w0[t] = 1.0f / (1.0f + expf(sec - best));
    }
}

// ---------------- kernel 1a: hierarchical scatter (256 global atomics total) ----------------
__global__ void scatter_kernel() {
    __shared__ int scnt[NEXP], sbase[NEXP];
    int tid = threadIdx.x;
    if (tid < NEXP) scnt[tid] = 0;
    __syncthreads();
    int base_t = blockIdx.x * 4096;
    int lr0[16], lr1[16];
#pragma unroll
    for (int r = 0; r < 16; r++) {
        int t = base_t + r * 256 + tid;
        uint32_t re = g_re[t];
        lr0[r] = atomicAdd(&scnt[re & 255], 1);
        lr1[r] = atomicAdd(&scnt[(re >> 8) & 255], 1);
    }
    __syncthreads();
    if (tid < NEXP) sbase[tid] = atomicAdd(&g_count[tid], scnt[tid]);
    __syncthreads();
#pragma unroll
    for (int r = 0; r < 16; r++) {
        int t = base_t + r * 256 + tid;
        uint32_t re = g_re[t];
        float w0 = g_w0[t];
        int e0 = re & 255, e1 = (re >> 8) & 255;
        int p0 = sbase[e0] + lr0[r];
        int p1 = sbase[e1] + lr1[r];
        g_tok[e0 * N_TOK + p0] = t;
        g_wt [e0 * N_TOK + p0] = w0;
        g_tok[e1 * N_TOK + p1] = t | (1 << 24);
        g_wt [e1 * N_TOK + p1] = 1.0f - w0;
    }
}

// ---------------- kernel 1b: pre-split weights into fp16 hi/lo ----------------
__global__ void wsplit_kernel(const float* __restrict__ W,
                              const float* __restrict__ Wl) {
    int idx = blockIdx.x * 256 + threadIdx.x;   // 196608 total
    int c4 = idx & 15;
    int k  = (idx >> 4) & 127;
    int ct = (idx >> 11) & 3;
    int rest = idx >> 13;
    int d = rest % 3, e = rest / 3;
    const float* src = (d == 0)
        ? W  + ((size_t)e * IN_F + k) * OUT_F + ct * 64 + c4 * 4
        : Wl + ((size_t)e * IN_F + k) * (2 * OUT_F) + (d == 2 ? OUT_F : 0) + ct * 64 + c4 * 4;
    float4 v = *(const float4*)src;
    uint32_t h01, l01, h23, l23;
    split2(v.x, v.y, h01, l01);
    split2(v.z, v.w, h23, l23);
    uint2 uh; uh.x = h01; uh.y = h23;
    uint2 ul; ul.x = l01; ul.y = l23;
    *(uint2*)&g_wsp[e][d][0][ct][k][c4 * 4] = uh;
    *(uint2*)&g_wsp[e][d][1][ct][k][c4 * 4] = ul;
}

// ---------------- kernel 2: 3-stage single-barrier split-fp16 mma pipeline ----------------
// 16 warps: wm = w>>2 (32-row band), wn = w&3 (16-col slice of the 64-col ctile)
__global__ __launch_bounds__(TH, 1) void expert_kernel(
    const float* __restrict__ x,  const float* __restrict__ lat,
    const float* __restrict__ b,  const float* __restrict__ bl)
{
    extern __shared__ __align__(16) __half sm[];
    __shared__ int   s_ent[TM];
    __shared__ float s_w[TM];

    int e = blockIdx.y;
    int cnt = g_count[e];
    int m0 = blockIdx.x * TM;
    if (m0 >= cnt) return;
    int rows = min(TM, cnt - m0);
    int tid = threadIdx.x;
    int w = tid >> 5, lane = tid & 31;

    uint32_t smu = smem_u32(sm);
    const __half* wb = &g_wsp[e][0][0][0][0][0];

    // ---- issue cp.async for chunks 0,1 (buf 0,1)
#pragma unroll
    for (int j = 0; j < 2; j++) {
        int kc0 = j * 32;
#pragma unroll
        for (int t = 0; t < 3; t++) {
            int u = t * TH + tid;
            int un = u & 7, r = (u >> 3) & 31, h = (u >> 8) & 1, d = u >> 9;
            const __half* src = wb + (size_t)(((d * 2 + h) * 4 * 128) + kc0 + r) * 64 + un * 8;
            uint32_t dst = smu + B_BASE_B
                         + (uint32_t)(j * CH + (d * 2 + h) * BT + r * 144 + un * 16);
            cp16(dst, src);
        }
        asm volatile("cp.async.commit_group;" ::: "memory");
    }

    if (tid < TM) {
        int ent = (tid < rows) ? g_tok[e * N_TOK + m0 + tid] : 0;
        s_ent[tid] = ent;
        s_w[tid]   = (tid < rows) ? g_wt[e * N_TOK + m0 + tid] : 0.0f;
    }
    __syncthreads();

    // ---- stage A: gather x/lat rows, split fp16 hi/lo (once per block)
#pragma unroll
    for (int s2 = 0; s2 < 2; s2++) {
        const float* src = s2 ? lat : x;
        __half* hiT = sm + (size_t)(s2 * 2) * (128 * SA);
#pragma unroll
        for (int it = 0; it < 8; it++) {
            int idx = it * TH + tid;
            int m = idx >> 5, k = (idx & 31) * 4;
            int tok = s_ent[m] & 0xFFFFFF;
            float4 v = *(const float4*)(src + (size_t)tok * IN_F + k);
            uint32_t h01, l01, h23, l23;
            split2(v.x, v.y, h01, l01);
            split2(v.z, v.w, h23, l23);
            __half* p = hiT + m * SA + k;
            uint2 uh; uh.x = h01; uh.y = h23;
            uint2 ul; ul.x = l01; ul.y = l23;
            *(uint2*)p = uh;
            *(uint2*)(p + 128 * SA) = ul;
        }
    }

    int wm = w >> 2, wn = w & 3;
    uint32_t aoff0 = (uint32_t)(((wm * 32 + (lane & 15)) * SA + (lane >> 4) * 8) * 2);
    uint32_t aoff1 = aoff0 + 16 * SA * 2;
    uint32_t bcon = (uint32_t)((((lane & 7) + ((lane >> 3) & 1) * 8) * SB
                               + ((lane >> 4) & 1) * 8 + wn * 16) * 2);

    float acc[3][2][2][4];
#pragma unroll
    for (int d = 0; d < 3; d++)
#pragma unroll
        for (int mf = 0; mf < 2; mf++)
#pragma unroll
            for (int nf = 0; nf < 2; nf++)
#pragma unroll
                for (int q = 0; q < 4; q++) acc[d][mf][nf][q] = 0.0f;

#pragma unroll 1
    for (int i = 0; i < 16; i++) {
        // chunk i must be complete; chunk i+1 may still be in flight
        if (i == 15) asm volatile("cp.async.wait_group 0;" ::: "memory");
        else         asm volatile("cp.async.wait_group 1;" ::: "memory");
        __syncthreads();   // all warps finished compute of iter i-1 (buf (i-1)%3 reusable)

        // ---- issue chunk i+2 into buf (i+2)%3 == (i-1)%3
        if (i <= 13) {
            int j = i + 2;
            int ct2 = j >> 2, kc0 = (j & 3) * 32, buf2 = j % 3;
#pragma unroll
            for (int t = 0; t < 3; t++) {
                int u = t * TH + tid;
                int un = u & 7, r = (u >> 3) & 31, h = (u >> 8) & 1, d = u >> 9;
                const __half* src = wb + (size_t)((((d * 2 + h) * 4 + ct2) * 128) + kc0 + r) * 64 + un * 8;
                uint32_t dst = smu + B_BASE_B
                             + (uint32_t)(buf2 * CH + (d * 2 + h) * BT + r * 144 + un * 16);
                cp16(dst, src);
            }
            asm volatile("cp.async.commit_group;" ::: "memory");
        }

        int c = i & 3, ct = i >> 2;
        uint32_t bB = smu + B_BASE_B + (uint32_t)(i % 3) * CH;

#pragma unroll
        for (int kl = 0; kl < 2; kl++) {
            uint32_t kby = (uint32_t)((c * 32 + kl * 16) * 2);
            uint32_t kbb = (uint32_t)(kl * 16 * SB * 2);
            uint32_t AH[2][4], AL[2][4];
            uint32_t bh[4], blo[4];

            // x fragments -> d0
            ldsm_x4(AH[0], smu + aoff0 + kby);
            ldsm_x4(AH[1], smu + aoff1 + kby);
            ldsm_x4(AL[0], smu + A_TILE_B + aoff0 + kby);
            ldsm_x4(AL[1], smu + A_TILE_B + aoff1 + kby);
            {
                ldsm_x4t(bh,  bB + bcon + kbb);
                ldsm_x4t(blo, bB + BT + bcon + kbb);
#pragma unroll
                for (int mf = 0; mf < 2; mf++)
#pragma unroll
                    for (int nf = 0; nf < 2; nf++) {
                        mma_f16(acc[0][mf][nf], AH[mf], &bh[nf * 2]);
                        mma_f16(acc[0][mf][nf], AH[mf], &blo[nf * 2]);
                        mma_f16(acc[0][mf][nf], AL[mf], &bh[nf * 2]);
                    }
            }
            // lat fragments -> d1, d2
            ldsm_x4(AH[0], smu + 2 * A_TILE_B + aoff0 + kby);
            ldsm_x4(AH[1], smu + 2 * A_TILE_B + aoff1 + kby);
            ldsm_x4(AL[0], smu + 3 * A_TILE_B + aoff0 + kby);
            ldsm_x4(AL[1], smu + 3 * A_TILE_B + aoff1 + kby);
#pragma unroll
            for (int d = 1; d < 3; d++) {
                uint32_t bhi = bB + (uint32_t)(d * 2) * BT;
                ldsm_x4t(bh,  bhi + bcon + kbb);
                ldsm_x4t(blo, bhi + BT + bcon + kbb);
#pragma unroll
                for (int mf = 0; mf < 2; mf++)
#pragma unroll
                    for (int nf = 0; nf < 2; nf++) {
                        mma_f16(acc[d][mf][nf], AH[mf], &bh[nf * 2]);
                        mma_f16(acc[d][mf][nf], AH[mf], &blo[nf * 2]);
                        mma_f16(acc[d][mf][nf], AL[mf], &bh[nf * 2]);
                    }
            }
        }

        // ---- epilogue at ctile end: bias + sin + gate weight + float2 stores
        if (c == 3) {
            int cb0 = ct * 64 + wn * 16 + 2 * (lane & 3);
            float2 Bb[2], Bs[2], Bt2[2];
#pragma unroll
            for (int nf = 0; nf < 2; nf++) {
                Bb[nf]  = *(const float2*)(b  + (size_t)e * OUT_F + cb0 + nf * 8);
                Bs[nf]  = *(const float2*)(bl + (size_t)e * 2 * OUT_F + cb0 + nf * 8);
                Bt2[nf] = *(const float2*)(bl + (size_t)e * 2 * OUT_F + OUT_F + cb0 + nf * 8);
            }
#pragma unroll
            for (int mf = 0; mf < 2; mf++)
#pragma unroll
                for (int hh = 0; hh < 2; hh++) {
                    int row = wm * 32 + mf * 16 + (lane >> 2) + 8 * hh;
                    if (row < rows) {
                        int ent = s_ent[row];
                        int tok = ent & 0xFFFFFF, sl = (ent >> 24) & 1;
                        float wt = s_w[row];
                        float* gp = &g_part[sl][tok][cb0];
#pragma unroll
                        for (int nf = 0; nf < 2; nf++) {
                            float hv0 = acc[0][mf][nf][2 * hh + 0] + Bb[nf].x;
                            float hv1 = acc[0][mf][nf][2 * hh + 1] + Bb[nf].y;
                            float sc0 = acc[1][mf][nf][2 * hh + 0] + Bs[nf].x;
                            float sc1 = acc[1][mf][nf][2 * hh + 1] + Bs[nf].y;
                            float sh0 = acc[2][mf][nf][2 * hh + 0] + Bt2[nf].x;
                            float sh1 = acc[2][mf][nf][2 * hh + 1] + Bt2[nf].y;
                            float2 o;
                            o.x = wt * fast_sin(fmaf(OMEGA * hv0, sc0, sh0));
                            o.y = wt * fast_sin(fmaf(OMEGA * hv1, sc1, sh1));
                            *(float2*)(gp + nf * 8) = o;
                        }
                    }
                }
            // reset accumulators for next ctile
#pragma unroll
            for (int d = 0; d < 3; d++)
#pragma unroll
                for (int mf = 0; mf < 2; mf++)
#pragma unroll
                    for (int nf = 0; nf < 2; nf++)
#pragma unroll
                        for (int q = 0; q < 4; q++) acc[d][mf][nf][q] = 0.0f;
        }
    }
}

// ---------------- kernel 3: combine slot contributions ----------------
__global__ void combine_kernel(float* __restrict__ out) {
    size_t i = (size_t)blockIdx.x * blockDim.x + threadIdx.x;
    const float4* p0 = (const float4*)&g_part[0][0][0];
    const float4* p1 = (const float4*)&g_part[1][0][0];
    float4 a = p0[i], c = p1[i];
    ((float4*)out)[i] = make_float4(a.x + c.x, a.y + c.y, a.z + c.z, a.w + c.w);
}

// ---------------- launch ----------------
extern "C" void kernel_launch(void* const* d_in, const int* in_sizes, int n_in,
                              void* d_out, int out_size) {
    const float* x   = (const float*)d_in[0];
    const float* lat = (const float*)d_in[1];
    const float* gw  = (const float*)d_in[2];
    const float* gb  = (const float*)d_in[3];
    const float* W   = (const float*)d_in[4];
    const float* b   = (const float*)d_in[5];
    const float* Wl  = (const float*)d_in[6];
    const float* bl  = (const float*)d_in[7];
    float* out = (float*)d_out;

    cudaFuncSetAttribute(expert_kernel,
                         cudaFuncAttributeMaxDynamicSharedMemorySize, SMEM_BYTES);

    init_kernel<<<1, 32>>>();
    route_kernel<<<N_TOK / 8, 256>>>(x, gw, gb);
    scatter_kernel<<<32, 256>>>();
    wsplit_kernel<<<768, 256>>>(W, Wl);
    cudaMemcpyAsync(out + (size_t)N_TOK * OUT_F, lat,
                    (size_t)N_TOK * IN_F * sizeof(float),
                    cudaMemcpyDeviceToDevice);
    expert_kernel<<<dim3(N_TOK / TM, NEXP), TH, SMEM_BYTES>>>(x, lat, b, bl);
    combine_kernel<<<(N_TOK * OUT_F / 4) / 256, 256>>>(out);
}